// round 8
// baseline (speedup 1.0000x reference)
#include <cuda_runtime.h>

// Problem constants
#define BQ   2
#define TT   1024
#define DD   1024
#define HH   16
#define DHD  64
#define KVL  3072
#define MEML 1024
#define CMEML 1024
#define SCALE_F 0.125f

// ---------------- scratch (device globals; no allocation) ----------------
__device__ float g_kv_in [(long)BQ * KVL * DD];        // tf32 bits
__device__ float g_q     [(long)BQ * TT  * DD];        // tf32 bits, pre-scaled
__device__ float g_kv_out[(long)BQ * KVL * 2 * DD];    // tf32 bits
__device__ float g_ctx   [(long)BQ * TT  * DD];        // tf32 bits
__device__ float g_wt    [4096L * 1024];               // tf32 bits
__device__ float g_xtf   [(long)BQ * TT * DD];
__device__ float g_wqt   [1024L * 1024];
__device__ float g_wkvt  [1024L * 2048];
__device__ float g_woutt [1024L * 1024];
__device__ float g_memtf [(long)BQ * MEML * DD];
__device__ float g_ptf   [(long)HH * KVL * DHD];

// ---------------- TF32 + cp.async helpers --------------------------------
__device__ __forceinline__ unsigned f2tf(float f) {
    unsigned u;
    asm("cvt.rna.tf32.f32 %0, %1;" : "=r"(u) : "f"(f));
    return u;
}
__device__ __forceinline__ void mma_tf32(float c[4], const unsigned a[4], const unsigned b[2]) {
    asm volatile(
        "mma.sync.aligned.m16n8k8.row.col.f32.tf32.tf32.f32 "
        "{%0,%1,%2,%3},{%4,%5,%6,%7},{%8,%9},{%0,%1,%2,%3};"
        : "+f"(c[0]), "+f"(c[1]), "+f"(c[2]), "+f"(c[3])
        : "r"(a[0]), "r"(a[1]), "r"(a[2]), "r"(a[3]), "r"(b[0]), "r"(b[1]));
}
__device__ __forceinline__ void cp16(void* s, const void* g) {
    unsigned a = (unsigned)__cvta_generic_to_shared(s);
    asm volatile("cp.async.cg.shared.global [%0], [%1], 16;" :: "r"(a), "l"(g));
}
__device__ __forceinline__ void cp_commit() { asm volatile("cp.async.commit_group;"); }
template<int N> __device__ __forceinline__ void cp_wait() {
    asm volatile("cp.async.wait_group %0;" :: "n"(N));
}

// ---------------- convert fp32 -> tf32 bits ------------------------------
__global__ void cvt_kernel(const float4* __restrict__ src, float* __restrict__ dst, long n4) {
    long i = (long)blockIdx.x * blockDim.x + threadIdx.x;
    if (i >= n4) return;
    float4 v = src[i];
    uint4 t;
    t.x = f2tf(v.x); t.y = f2tf(v.y); t.z = f2tf(v.z); t.w = f2tf(v.w);
    *(uint4*)(dst + i * 4) = t;
}

// ---------------- kv concat: [cmem, mem, x] -> g_kv_in (tf32) -------------
__global__ void concat_kv_kernel(const float* __restrict__ x,
                                 const float* __restrict__ mem,
                                 const float* __restrict__ cmem) {
    long i4 = (long)blockIdx.x * blockDim.x + threadIdx.x;
    const long total4 = (long)BQ * KVL * DD / 4;
    if (i4 >= total4) return;
    long e = i4 * 4;
    int  b   = (int)(e / ((long)KVL * DD));
    long rem = e - (long)b * KVL * DD;
    int  t   = (int)(rem / DD);
    int  c   = (int)(rem - (long)t * DD);
    const float* src;
    if (t < CMEML)              src = cmem + (long)b * CMEML * DD + (long)t * DD + c;
    else if (t < CMEML + MEML)  src = mem  + (long)b * MEML  * DD + (long)(t - CMEML) * DD + c;
    else                        src = x    + (long)b * TT    * DD + (long)(t - CMEML - MEML) * DD + c;
    float4 v = *(const float4*)src;
    uint4 tv;
    tv.x = f2tf(v.x); tv.y = f2tf(v.y); tv.z = f2tf(v.z); tv.w = f2tf(v.w);
    *(uint4*)(g_kv_in + e) = tv;
}

// ---------------- async TF32 MMA GEMM (inputs pre-converted) --------------
template<int BM, int BN, int WM, int WN, bool TF32OUT>
__global__ __launch_bounds__(256) void mma_gemm_async(
    const float* __restrict__ A, const float* __restrict__ B,
    const float* __restrict__ bias, float* __restrict__ C,
    int K, int lda, int ldb, int ldc, float alpha, int ZH,
    long sAb, long sAh, long sBb, long sBh, long sCb, long sCh)
{
    int z = blockIdx.z;
    int zb = z / ZH, zh = z - zb * ZH;
    A += (long)zb * sAb + (long)zh * sAh;
    B += (long)zb * sBb + (long)zh * sBh;
    C += (long)zb * sCb + (long)zh * sCh;
    int m0 = blockIdx.y * BM, n0 = blockIdx.x * BN;

    __shared__ __align__(16) unsigned As[2][BM][20];
    __shared__ __align__(16) unsigned Bs[2][16][BN + 8];

    int tid  = threadIdx.x;
    int warp = tid >> 5, lane = tid & 31;
    int gid  = lane >> 2, tg = lane & 3;
    constexpr int WNN = BN / WN;
    int wm = warp / WNN, wn = warp % WNN;
    constexpr int MI = WM / 16, NI = WN / 8;

    float acc[MI][NI][4];
    #pragma unroll
    for (int mi = 0; mi < MI; mi++)
        #pragma unroll
        for (int ni = 0; ni < NI; ni++)
            #pragma unroll
            for (int u = 0; u < 4; u++) acc[mi][ni][u] = 0.f;

    auto issueTiles = [&](int k0, int buf) {
        #pragma unroll
        for (int i = 0; i < BM / 64; i++) {
            int f = tid + i * 256;
            int r = f >> 2, c = (f & 3) << 2;
            cp16(&As[buf][r][c], A + (long)(m0 + r) * lda + k0 + c);
        }
        constexpr int B4 = BN / 4;
        #pragma unroll
        for (int i = 0; i < BN / 64; i++) {
            int f = tid + i * 256;
            int r = f / B4, c = (f % B4) * 4;
            cp16(&Bs[buf][r][c], B + (long)(k0 + r) * ldb + n0 + c);
        }
        cp_commit();
    };

    issueTiles(0, 0);
    int nk = K / 16;
    for (int kt = 0; kt < nk; kt++) {
        int buf = kt & 1;
        if (kt + 1 < nk) {
            __syncthreads();
            issueTiles((kt + 1) * 16, buf ^ 1);
            cp_wait<1>();
        } else {
            cp_wait<0>();
        }
        __syncthreads();
        #pragma unroll
        for (int ks = 0; ks < 16; ks += 8) {
            unsigned af[MI][4], bf[NI][2];
            #pragma unroll
            for (int mi = 0; mi < MI; mi++) {
                int r = wm * WM + mi * 16;
                af[mi][0] = As[buf][r + gid][ks + tg];
                af[mi][1] = As[buf][r + gid + 8][ks + tg];
                af[mi][2] = As[buf][r + gid][ks + tg + 4];
                af[mi][3] = As[buf][r + gid + 8][ks + tg + 4];
            }
            #pragma unroll
            for (int ni = 0; ni < NI; ni++) {
                int cb = wn * WN + ni * 8;
                bf[ni][0] = Bs[buf][ks + tg][cb + gid];
                bf[ni][1] = Bs[buf][ks + tg + 4][cb + gid];
            }
            #pragma unroll
            for (int mi = 0; mi < MI; mi++)
                #pragma unroll
                for (int ni = 0; ni < NI; ni++)
                    mma_tf32(acc[mi][ni], af[mi], bf[ni]);
        }
    }

    #pragma unroll
    for (int mi = 0; mi < MI; mi++) {
        #pragma unroll
        for (int ni = 0; ni < NI; ni++) {
            int r0 = m0 + wm * WM + mi * 16 + gid;
            int c  = n0 + wn * WN + ni * 8 + 2 * tg;
            if (TF32OUT) {
                uint2 v0 = make_uint2(f2tf(alpha * acc[mi][ni][0]), f2tf(alpha * acc[mi][ni][1]));
                uint2 v1 = make_uint2(f2tf(alpha * acc[mi][ni][2]), f2tf(alpha * acc[mi][ni][3]));
                *(uint2*)(C + (long)r0 * ldc + c)       = v0;
                *(uint2*)(C + (long)(r0 + 8) * ldc + c) = v1;
            } else {
                float b0 = 0.f, b1 = 0.f;
                if (bias) { b0 = bias[c]; b1 = bias[c + 1]; }
                float2 v0 = make_float2(alpha * acc[mi][ni][0] + b0, alpha * acc[mi][ni][1] + b1);
                float2 v1 = make_float2(alpha * acc[mi][ni][2] + b0, alpha * acc[mi][ni][3] + b1);
                *(float2*)(C + (long)r0 * ldc + c)       = v0;
                *(float2*)(C + (long)(r0 + 8) * ldc + c) = v1;
            }
        }
    }
}

// ---------------- fused flash attention: 4 warps, 2 CTAs/SM ---------------
// i-tile = 64 rows, j-tile = 64. Grid (1, 16, 32) = 512 CTAs.
// smem (109568 B, fits 2 CTAs/SM):
//   Ks[2][64][68] u32 @0      (34816)  double-buffered
//   Vs[64][72]    u32 @34816  (18432)  single
//   Ps[128][68]   u32 @53248  (34816)  single (pos band, 127 rows used)
//   Pg[64][84]    f32 @88064  (21504)  warp-private bounce
// Pipeline (FIFO cp.async groups): A_t = {K_t, P_t}, B_t = {V_t}.
//   top:    wait<1> (completes A_t) ; sync
//   S/P MMA; sync; issue A_{t+1}
//   softmax (regs + Pg, warp-local)
//   wait<1> (completes B_t; A_{t+1} stays in flight); sync
//   AV MMA; sync; issue B_{t+1}
#define FL_SMEM 109568

__global__ __launch_bounds__(128, 2) void flash_kernel(const float* __restrict__ pos_tf) {
    extern __shared__ __align__(16) unsigned char sm[];
    unsigned (*Ks)[64][68] = (unsigned(*)[64][68])(sm);
    unsigned (*Vs)[72]     = (unsigned(*)[72])   (sm + 34816);
    unsigned (*Ps)[68]     = (unsigned(*)[68])   (sm + 53248);
    float    (*Pg)[84]     = (float(*)[84])      (sm + 88064);

    int bh = blockIdx.z; int b = bh >> 4, h = bh & 15;
    int i0 = blockIdx.y << 6;
    int tid = threadIdx.x, warp = tid >> 5, lane = tid & 31;
    int gid = lane >> 2, tg = lane & 3;

    // Q fragments in registers (g_q already scaled & tf32)
    unsigned qf[8][4];
    {
        const float* q0 = g_q + (long)(b * TT + i0 + (warp << 4) + gid) * DD + h * DHD;
        const float* q1 = q0 + 8 * DD;
        #pragma unroll
        for (int kb = 0; kb < 8; kb++) {
            qf[kb][0] = __float_as_uint(q0[kb * 8 + tg]);
            qf[kb][1] = __float_as_uint(q1[kb * 8 + tg]);
            qf[kb][2] = __float_as_uint(q0[kb * 8 + tg + 4]);
            qf[kb][3] = __float_as_uint(q1[kb * 8 + tg + 4]);
        }
    }

    int r2 = tid >> 1, cw = (tid & 1) << 5;      // row 0..63, col 0/32
    const float* kvbase = g_kv_out + ((long)(b * KVL) + r2) * (2 * DD) + h * DHD + cw;
    int ub0 = 960 - i0;                          // band row 0 -> pos index j0+ub0

    auto issueKP = [&](int j0, int kb) {
        const float* kp = kvbase + (long)j0 * (2 * DD);
        #pragma unroll
        for (int u = 0; u < 8; u++) cp16(&Ks[kb][r2][cw + 4 * u], kp + 4 * u);
        int ub = j0 + ub0;
        #pragma unroll
        for (int half = 0; half < 2; half++) {
            int rr = r2 + (half << 6);
            int uu = ub + rr;
            if (uu < KVL) {
                const float* pp = pos_tf + ((long)h * KVL + uu) * DHD + cw;
                #pragma unroll
                for (int q = 0; q < 8; q++) cp16(&Ps[rr][cw + 4 * q], pp + 4 * q);
            } else {
                uint4 z = make_uint4(0, 0, 0, 0);
                #pragma unroll
                for (int q = 0; q < 8; q++) *(uint4*)&Ps[rr][cw + 4 * q] = z;
            }
        }
        cp_commit();
    };
    auto issueV = [&](int j0) {
        const float* vp = kvbase + (long)j0 * (2 * DD) + DD;
        #pragma unroll
        for (int u = 0; u < 8; u++) cp16(&Vs[r2][cw + 4 * u], vp + 4 * u);
        cp_commit();
    };

    float oacc[8][4] = {};
    float m0r = -1e30f, m1r = -1e30f, l0r = 0.f, l1r = 0.f;
    int wb = 48 - (warp << 4);                   // band window start for this warp
    int pgr0 = (warp << 4) + gid, pgr1 = pgr0 + 8;

    issueKP(0, 0);
    issueV(0);
    for (int t = 0; t < 48; t++) {
        int buf = t & 1;
        cp_wait<1>();            // completes A_t (K,P); B_t (V) may still fly
        __syncthreads();

        // ---- S = QK^T and band product ----
        float sacc[8][4] = {}, pacc[10][4] = {};
        #pragma unroll
        for (int kb = 0; kb < 8; kb++) {
            #pragma unroll
            for (int nb = 0; nb < 8; nb++) {
                unsigned bf[2] = { Ks[buf][nb * 8 + gid][kb * 8 + tg],
                                   Ks[buf][nb * 8 + gid][kb * 8 + tg + 4] };
                mma_tf32(sacc[nb], qf[kb], bf);
            }
            #pragma unroll
            for (int nb = 0; nb < 10; nb++) {
                unsigned bf[2] = { Ps[wb + nb * 8 + gid][kb * 8 + tg],
                                   Ps[wb + nb * 8 + gid][kb * 8 + tg + 4] };
                mma_tf32(pacc[nb], qf[kb], bf);
            }
        }
        __syncthreads();         // all warps done reading Ks[buf] & Ps
        if (t + 1 < 48) issueKP((t + 1) << 6, buf ^ 1);   // group A_{t+1}

        // ---- dump band product, gather shifted into S (warp-local) ----
        #pragma unroll
        for (int nb = 0; nb < 10; nb++) {
            Pg[pgr0][nb * 8 + 2 * tg]     = pacc[nb][0];
            Pg[pgr0][nb * 8 + 2 * tg + 1] = pacc[nb][1];
            Pg[pgr1][nb * 8 + 2 * tg]     = pacc[nb][2];
            Pg[pgr1][nb * 8 + 2 * tg + 1] = pacc[nb][3];
        }
        __syncwarp();
        {
            int s0 = 15 - gid, s1 = 7 - gid;
            #pragma unroll
            for (int nb = 0; nb < 8; nb++) {
                int jl = nb * 8 + 2 * tg;
                sacc[nb][0] += Pg[pgr0][jl + s0];
                sacc[nb][1] += Pg[pgr0][jl + 1 + s0];
                sacc[nb][2] += Pg[pgr1][jl + s1];
                sacc[nb][3] += Pg[pgr1][jl + 1 + s1];
            }
        }

        // ---- online softmax (rows quad-local) ----
        float mx0 = -1e30f, mx1 = -1e30f;
        #pragma unroll
        for (int nb = 0; nb < 8; nb++) {
            mx0 = fmaxf(mx0, fmaxf(sacc[nb][0], sacc[nb][1]));
            mx1 = fmaxf(mx1, fmaxf(sacc[nb][2], sacc[nb][3]));
        }
        #pragma unroll
        for (int o = 1; o <= 2; o <<= 1) {
            mx0 = fmaxf(mx0, __shfl_xor_sync(0xffffffffu, mx0, o));
            mx1 = fmaxf(mx1, __shfl_xor_sync(0xffffffffu, mx1, o));
        }
        float mn0 = fmaxf(m0r, mx0), mn1 = fmaxf(m1r, mx1);
        float f0 = __expf(m0r - mn0), f1 = __expf(m1r - mn1);
        m0r = mn0; m1r = mn1;
        float ps0 = 0.f, ps1 = 0.f;
        #pragma unroll
        for (int nb = 0; nb < 8; nb++) {
            sacc[nb][0] = __expf(sacc[nb][0] - mn0);
            sacc[nb][1] = __expf(sacc[nb][1] - mn0);
            sacc[nb][2] = __expf(sacc[nb][2] - mn1);
            sacc[nb][3] = __expf(sacc[nb][3] - mn1);
            ps0 += sacc[nb][0] + sacc[nb][1];
            ps1 += sacc[nb][2] + sacc[nb][3];
            oacc[nb][0] *= f0; oacc[nb][1] *= f0;
            oacc[nb][2] *= f1; oacc[nb][3] *= f1;
        }
        #pragma unroll
        for (int o = 1; o <= 2; o <<= 1) {
            ps0 += __shfl_xor_sync(0xffffffffu, ps0, o);
            ps1 += __shfl_xor_sync(0xffffffffu, ps1, o);
        }
        l0r = l0r * f0 + ps0;
        l1r = l1r * f1 + ps1;

        // ---- probs -> Pg (tf32) -> A fragments (warp-local) ----
        __syncwarp();
        #pragma unroll
        for (int nb = 0; nb < 8; nb++) {
            Pg[pgr0][nb * 8 + 2 * tg]     = __uint_as_float(f2tf(sacc[nb][0]));
            Pg[pgr0][nb * 8 + 2 * tg + 1] = __uint_as_float(f2tf(sacc[nb][1]));
            Pg[pgr1][nb * 8 + 2 * tg]     = __uint_as_float(f2tf(sacc[nb][2]));
            Pg[pgr1][nb * 8 + 2 * tg + 1] = __uint_as_float(f2tf(sacc[nb][3]));
        }
        __syncwarp();

        // ---- wait for V_t, then AV ----
        if (t + 1 < 48) cp_wait<1>(); else cp_wait<0>();
        __syncthreads();
        #pragma unroll
        for (int kb = 0; kb < 8; kb++) {
            unsigned af[4];
            af[0] = __float_as_uint(Pg[pgr0][kb * 8 + tg]);
            af[1] = __float_as_uint(Pg[pgr1][kb * 8 + tg]);
            af[2] = __float_as_uint(Pg[pgr0][kb * 8 + tg + 4]);
            af[3] = __float_as_uint(Pg[pgr1][kb * 8 + tg + 4]);
            #pragma unroll
            for (int nb = 0; nb < 8; nb++) {
                unsigned bf[2] = { Vs[kb * 8 + tg][nb * 8 + gid],
                                   Vs[kb * 8 + tg + 4][nb * 8 + gid] };
                mma_tf32(oacc[nb], af, bf);
            }
        }
        __syncthreads();         // all warps done reading Vs
        if (t + 1 < 48) issueV((t + 1) << 6);             // group B_{t+1}
    }

    // ---- write ctx = O / l as tf32 bits (consumed by out-proj GEMM) ----
    float inv0 = 1.0f / l0r, inv1 = 1.0f / l1r;
    #pragma unroll
    for (int nb = 0; nb < 8; nb++) {
        int c = h * DHD + nb * 8 + 2 * tg;
        long r0 = (long)(b * TT + i0 + (warp << 4) + gid) * DD + c;
        uint2 v0 = make_uint2(f2tf(oacc[nb][0] * inv0), f2tf(oacc[nb][1] * inv0));
        uint2 v1 = make_uint2(f2tf(oacc[nb][2] * inv1), f2tf(oacc[nb][3] * inv1));
        *(uint2*)(g_ctx + r0)          = v0;
        *(uint2*)(g_ctx + r0 + 8 * DD) = v1;
    }
}

// ---------------- conv weight transpose (tf32 out) ------------------------
__global__ void wtrans_kernel(const float* __restrict__ w) {
    long idx = (long)blockIdx.x * blockDim.x + threadIdx.x;
    if (idx >= 4096L * 1024) return;
    int k = (int)(idx >> 10);
    int o = (int)(idx & 1023);
    g_wt[idx] = __uint_as_float(f2tf(w[(long)o * 4096 + ((k & 1023) << 2) + (k >> 10)]));
}

// ---------------- simple vectorized copy + aux ---------------------------
__global__ void copy4_kernel(const float4* __restrict__ src, float4* __restrict__ dst, long n4) {
    long i = (long)blockIdx.x * blockDim.x + threadIdx.x;
    if (i < n4) dst[i] = src[i];
}
__global__ void aux_kernel(float* out) { *out = 0.f; }

// ---------------- launch ---------------------------------------------------
extern "C" void kernel_launch(void* const* d_in, const int* in_sizes, int n_in,
                              void* d_out_, int out_size) {
    const float* x      = (const float*)d_in[0];
    const float* mem    = (const float*)d_in[1];
    const float* cmem   = (const float*)d_in[2];
    const float* pos    = (const float*)d_in[3];
    const float* Wq     = (const float*)d_in[4];
    const float* Wkv    = (const float*)d_in[5];
    const float* Wout   = (const float*)d_in[6];
    const float* b_out  = (const float*)d_in[7];
    const float* conv_w = (const float*)d_in[8];
    const float* conv_b = (const float*)d_in[9];
    float* out = (float*)d_out_;

    float *p_kvin, *p_q, *p_kvout, *p_ctx, *p_wt;
    float *p_xtf, *p_wqt, *p_wkvt, *p_woutt, *p_memtf, *p_ptf;
    cudaGetSymbolAddress((void**)&p_kvin,  g_kv_in);
    cudaGetSymbolAddress((void**)&p_q,     g_q);
    cudaGetSymbolAddress((void**)&p_kvout, g_kv_out);
    cudaGetSymbolAddress((void**)&p_ctx,   g_ctx);
    cudaGetSymbolAddress((void**)&p_wt,    g_wt);
    cudaGetSymbolAddress((void**)&p_xtf,   g_xtf);
    cudaGetSymbolAddress((void**)&p_wqt,   g_wqt);
    cudaGetSymbolAddress((void**)&p_wkvt,  g_wkvt);
    cudaGetSymbolAddress((void**)&p_woutt, g_woutt);
    cudaGetSymbolAddress((void**)&p_memtf, g_memtf);
    cudaGetSymbolAddress((void**)&p_ptf,   g_ptf);

    cudaFuncSetAttribute(flash_kernel, cudaFuncAttributeMaxDynamicSharedMemorySize, FL_SMEM);

    // pre-convert operands to tf32 bits
    concat_kv_kernel<<<6144, 256>>>(x, mem, cmem);
    cvt_kernel<<<2048, 256>>>((const float4*)x,    p_xtf,   524288);
    cvt_kernel<<<1024, 256>>>((const float4*)Wq,   p_wqt,   262144);
    cvt_kernel<<<2048, 256>>>((const float4*)Wkv,  p_wkvt,  524288);
    cvt_kernel<<<1024, 256>>>((const float4*)Wout, p_woutt, 262144);
    cvt_kernel<<<2048, 256>>>((const float4*)mem,  p_memtf, 524288);
    cvt_kernel<<<3072, 256>>>((const float4*)pos,  p_ptf,   786432);
    wtrans_kernel<<<16384, 256>>>(conv_w);

    // q = SCALE * x @ Wq  (tf32 out, pre-scaled for attention)
    mma_gemm_async<128,128,64,32,true><<<dim3(8, 16, 1), 256>>>(
        p_xtf, p_wqt, nullptr, p_q, 1024, 1024, 1024, 1024, SCALE_F, 1, 0,0, 0,0, 0,0);
    // kv = kv_in @ Wkv  (tf32 out)
    mma_gemm_async<128,128,64,32,true><<<dim3(16, 48, 1), 256>>>(
        p_kvin, p_wkvt, nullptr, p_kvout, 1024, 1024, 2048, 2048, 1.0f, 1, 0,0, 0,0, 0,0);

    // fused attention (4-warp CTAs, 2 per SM)
    flash_kernel<<<dim3(1, 16, 32), 128, FL_SMEM>>>(p_ptf);

    // logits = ctx @ Wout + b_out
    mma_gemm_async<128,128,64,32,false><<<dim3(8, 16, 1), 256>>>(
        p_ctx, p_woutt, b_out, out, 1024, 1024, 1024, 1024, 1.0f, 1, 0,0, 0,0, 0,0);

    // new_mem = x
    copy4_kernel<<<2048, 256>>>((const float4*)x, (float4*)(out + 2097152), 524288);

    // new_cmem part 1: cmem[:, 256:]
    copy4_kernel<<<768, 256>>>((const float4*)(cmem + 262144),  (float4*)(out + 4194304), 196608);
    copy4_kernel<<<768, 256>>>((const float4*)(cmem + 1310720), (float4*)(out + 5242880), 196608);

    // new_cmem part 2: conv as GEMM (M=256, K=4096, N=1024) per batch
    mma_gemm_async<128,128,64,32,false><<<dim3(8, 2, 2), 256>>>(
        p_memtf, p_wt, conv_b, out + 4980736, 4096, 4096, 1024, 1024, 1.0f, 1,
        1048576L, 0L, 0L, 0L, 1048576L, 0L);

    // aux_loss = 0
    aux_kernel<<<1, 1>>>(out + 6291456);
}